// round 4
// baseline (speedup 1.0000x reference)
#include <cuda_runtime.h>

// Fused Canny front-end: separable 5-tap Gaussian + Sobel + magnitude threshold.
// The reference's NMS / orientation path is dead code w.r.t. the output
// (it returns early_threshold which depends only on grad_mag).
//
// Boundary semantics: the reference zero-pads the *blurred* tensor before the
// Sobel stage, so blurred values outside the image domain must be exactly 0.
// Stage 2 masks accordingly.

#define TX 128           // output tile width
#define TY 32            // output tile height
#define IW (TX + 6)      // 134 input tile cols (halo 3)
#define IH (TY + 6)      // 38  input tile rows
#define ISTR (IW + 2)    // 136 padded stride
#define HWC (TX + 2)     // 130 h-gauss cols (halo 1 for sobel)
#define HSTR (HWC + 2)   // 132 padded stride

__global__ __launch_bounds__(256) void canny_fused_kernel(
    const float* __restrict__ img,
    const float* __restrict__ g5,     // gaussian 1d, 5 taps
    const float* __restrict__ sh9,    // sobel_h 3x3
    const float* __restrict__ sv9,    // sobel_v 3x3
    float* __restrict__ out,
    int W, int H)
{
    __shared__ float sA[IH * ISTR];   // input tile, later reused for blurred
    __shared__ float sB[IH * HSTR];   // horizontal-gauss intermediate

    const int tx = threadIdx.x;       // 0..31
    const int ty = threadIdx.y;       // 0..7
    const int x0 = blockIdx.x * TX;
    const int y0 = blockIdx.y * TY;
    const long plane = (long)W * H;
    const float* im = img + (long)blockIdx.z * plane;
    float* o = out + (long)blockIdx.z * plane;

    const float g0 = __ldg(g5 + 0), g1 = __ldg(g5 + 1), g2 = __ldg(g5 + 2),
                g3 = __ldg(g5 + 3), g4 = __ldg(g5 + 4);

    // ---- stage 0: load input tile with zero-pad halo (3) ----
    #pragma unroll
    for (int r = ty; r < IH; r += 8) {
        const int gy = y0 + r - 3;
        const bool rv = (gy >= 0) && (gy < H);
        const float* row = im + (long)gy * W;
        #pragma unroll
        for (int c = tx; c < IW; c += 32) {
            const int gx = x0 + c - 3;
            float v = 0.0f;
            if (rv && gx >= 0 && gx < W) v = __ldg(row + gx);
            sA[r * ISTR + c] = v;
        }
    }
    __syncthreads();

    // ---- stage 1: horizontal gaussian (sA -> sB) ----
    // sB col c corresponds to image x = x0 + c - 1
    #pragma unroll
    for (int r = ty; r < IH; r += 8) {
        const float* row = &sA[r * ISTR];
        #pragma unroll
        for (int c = tx; c < HWC; c += 32) {
            sB[r * HSTR + c] = g0 * row[c]     + g1 * row[c + 1] + g2 * row[c + 2]
                             + g3 * row[c + 3] + g4 * row[c + 4];
        }
    }
    __syncthreads();

    // ---- stage 2: vertical gaussian (sB -> sA reuse), masked to image domain ----
    // blurred row r corresponds to image y = y0 + r - 1, col c to x = x0 + c - 1.
    // Reference zero-pads the blurred tensor before Sobel, so anything outside
    // [0,H)x[0,W) must be exactly 0.
    #pragma unroll
    for (int r = ty; r < TY + 2; r += 8) {
        const int by = y0 + r - 1;
        const bool yv = (by >= 0) && (by < H);
        #pragma unroll
        for (int c = tx; c < HWC; c += 32) {
            const int bx = x0 + c - 1;
            const float* col = &sB[r * HSTR + c];
            float v = g0 * col[0]        + g1 * col[HSTR]     + g2 * col[2 * HSTR]
                    + g3 * col[3 * HSTR] + g4 * col[4 * HSTR];
            const bool valid = yv && (bx >= 0) && (bx < W);
            sA[r * ISTR + c] = valid ? v : 0.0f;
        }
    }
    __syncthreads();

    // ---- stage 3: sobel + magnitude + threshold ----
    const float h00 = __ldg(sh9 + 0), h01 = __ldg(sh9 + 1), h02 = __ldg(sh9 + 2),
                h10 = __ldg(sh9 + 3), h11 = __ldg(sh9 + 4), h12 = __ldg(sh9 + 5),
                h20 = __ldg(sh9 + 6), h21 = __ldg(sh9 + 7), h22 = __ldg(sh9 + 8);
    const float v00 = __ldg(sv9 + 0), v01 = __ldg(sv9 + 1), v02 = __ldg(sv9 + 2),
                v10 = __ldg(sv9 + 3), v11 = __ldg(sv9 + 4), v12 = __ldg(sv9 + 5),
                v20 = __ldg(sv9 + 6), v21 = __ldg(sv9 + 7), v22 = __ldg(sv9 + 8);

    #pragma unroll
    for (int r = ty; r < TY; r += 8) {
        float* orow = o + (long)(y0 + r) * W + x0;
        #pragma unroll
        for (int c = tx; c < TX; c += 32) {
            // output (r,c) -> blurred center row r+1, col c+1; 3x3 window rows r..r+2, cols c..c+2
            const float* b0 = &sA[r * ISTR + c];
            const float* b1 = b0 + ISTR;
            const float* b2 = b1 + ISTR;
            const float a00 = b0[0], a01 = b0[1], a02 = b0[2];
            const float a10 = b1[0], a11 = b1[1], a12 = b1[2];
            const float a20 = b2[0], a21 = b2[1], a22 = b2[2];

            float gx = h00 * a00 + h01 * a01 + h02 * a02
                     + h10 * a10 + h11 * a11 + h12 * a12
                     + h20 * a20 + h21 * a21 + h22 * a22;
            float gy = v00 * a00 + v01 * a01 + v02 * a02
                     + v10 * a10 + v11 * a11 + v12 * a12
                     + v20 * a20 + v21 * a21 + v22 * a22;

            float mag = sqrtf(gx * gx + gy * gy);
            orow[c] = (mag < 2.0f) ? 0.0f : mag;
        }
    }
}

extern "C" void kernel_launch(void* const* d_in, const int* in_sizes, int n_in,
                              void* d_out, int out_size) {
    // metadata order: img, gauss_h, gauss_v, sobel_h, sobel_v, dir_w
    const float* img     = (const float*)d_in[0];
    const float* gauss_h = (const float*)d_in[1];   // 5 taps (same as gauss_v)
    const float* sobel_h = (const float*)d_in[3];
    const float* sobel_v = (const float*)d_in[4];
    float* out = (float*)d_out;

    const int W = 1024, H = 1024;
    const int N = in_sizes[0] / (W * H);

    dim3 block(32, 8, 1);
    dim3 grid(W / TX, H / TY, N);
    canny_fused_kernel<<<grid, block>>>(img, gauss_h, sobel_h, sobel_v, out, W, H);
}

// round 5
// speedup vs baseline: 1.6828x; 1.6828x over previous
#include <cuda_runtime.h>

// Fused Canny front-end (separable 5-tap Gaussian + Sobel + magnitude threshold).
// The reference's NMS/orientation path is dead code w.r.t. the output.
//
// v2: all-float4 smem pipeline; vertical-gaussian + sobel fused into registers
// (4x4 patch per thread), sobel computed via its separable factorization.
// Boundary: the reference zero-pads the *blurred* tensor before Sobel, so
// blurred values outside the image domain are masked to 0 (edge CTAs only).

#define TX 128
#define TY 32
#define IROWS 38           // image rows y0-3 .. y0+34
#define AF4   36           // raw tile:  cols x0-8 .. x0+135 (144 floats)
#define BF4   34           // hgauss:    cols x0-4 .. x0+131 (136 floats)

__global__ __launch_bounds__(256) void canny_fused_v2(
    const float* __restrict__ img,
    const float* __restrict__ g5,     // gaussian 1d, 5 taps
    float* __restrict__ out,
    int W, int H)
{
    __shared__ float4 sA[IROWS * AF4];   // raw input tile (zero-padded halo)
    __shared__ float4 sB[IROWS * BF4];   // horizontal-gauss intermediate

    const int tx = threadIdx.x;          // 0..31
    const int ty = threadIdx.y;          // 0..7
    const int t  = ty * 32 + tx;
    const int x0 = blockIdx.x * TX;
    const int y0 = blockIdx.y * TY;
    const long plane = (long)W * H;
    const float* im = img + (long)blockIdx.z * plane;
    float* o = out + (long)blockIdx.z * plane;

    const float g0 = __ldg(g5 + 0), g1 = __ldg(g5 + 1), g2 = __ldg(g5 + 2),
                g3 = __ldg(g5 + 3), g4 = __ldg(g5 + 4);

    // ---- stage 0: vectorized load, zero-pad halo ----
    // Every halo float4 is fully in-range or fully out-of-range (W,x0 mult of 4).
    #pragma unroll 2
    for (int i = t; i < IROWS * AF4; i += 256) {
        const int r  = i / AF4;
        const int q  = i - r * AF4;
        const int gy = y0 + r - 3;
        const int gx = x0 - 8 + 4 * q;
        float4 v = make_float4(0.f, 0.f, 0.f, 0.f);
        if ((unsigned)gy < (unsigned)H && (unsigned)gx < (unsigned)W)
            v = *(const float4*)(im + (long)gy * W + gx);
        sA[i] = v;
    }
    __syncthreads();

    // ---- stage 1: horizontal gaussian, float4 in / float4 out ----
    // sB col j (float) = image x0-4+j ; output f4 q covers floats 4q..4q+3,
    // needs sA floats 4q+2 .. 4q+9  (sA float j = image x0-8+j).
    #pragma unroll 2
    for (int i = t; i < IROWS * BF4; i += 256) {
        const int r = i / BF4;
        const int q = i - r * BF4;
        const float4 A = sA[r * AF4 + q];
        const float4 B = sA[r * AF4 + q + 1];
        const float4 C = sA[r * AF4 + q + 2];
        float4 oo;
        oo.x = g0 * A.z + g1 * A.w + g2 * B.x + g3 * B.y + g4 * B.z;
        oo.y = g0 * A.w + g1 * B.x + g2 * B.y + g3 * B.z + g4 * B.w;
        oo.z = g0 * B.x + g1 * B.y + g2 * B.z + g3 * B.w + g4 * C.x;
        oo.w = g0 * B.y + g1 * B.z + g2 * B.w + g3 * C.x + g4 * C.y;
        sB[i] = oo;
    }
    __syncthreads();

    // ---- stage 2+3 fused in registers: vertical gaussian -> sobel -> mag ----
    // Thread patch: output rows y0+4ty..+3, cols x0+4tx..+3.
    // Blurred needed: rows br=0..5 (y = y0+4ty-1+br), cols c=0..5 (x = x0+4tx-1+c).
    // sB rows needed: 4ty .. 4ty+9 ; sB floats 4tx+3..4tx+8 -> f4 idx tx,tx+1,tx+2.
    const float gt[5] = {g0, g1, g2, g3, g4};
    float b[6][6];
    #pragma unroll
    for (int i = 0; i < 6; i++)
        #pragma unroll
        for (int j = 0; j < 6; j++) b[i][j] = 0.f;

    #pragma unroll
    for (int k = 0; k < 10; k++) {
        const float4* brow = &sB[(4 * ty + k) * BF4 + tx];
        const float4 P = brow[0];
        const float4 Q = brow[1];
        const float4 R = brow[2];
        const float v0 = P.w, v1 = Q.x, v2 = Q.y, v3 = Q.z, v4 = Q.w, v5 = R.x;
        #pragma unroll
        for (int br = 0; br < 6; br++) {
            const int ki = k - br;
            if (ki >= 0 && ki < 5) {
                const float gg = gt[ki];
                b[br][0] += gg * v0;  b[br][1] += gg * v1;
                b[br][2] += gg * v2;  b[br][3] += gg * v3;
                b[br][4] += gg * v4;  b[br][5] += gg * v5;
            }
        }
    }

    // Zero-pad mask for the blurred tensor (reference semantics). Edge CTAs only.
    if (x0 == 0 || x0 + TX == W || y0 == 0 || y0 + TY == H) {
        const int by = y0 + 4 * ty - 1;
        const int bx = x0 + 4 * tx - 1;
        #pragma unroll
        for (int br = 0; br < 6; br++) {
            const bool yv = (unsigned)(by + br) < (unsigned)H;
            #pragma unroll
            for (int c = 0; c < 6; c++) {
                const bool xv = (unsigned)(bx + c) < (unsigned)W;
                if (!(yv && xv)) b[br][c] = 0.f;
            }
        }
    }

    // Separable sobel: sobel_h = [1,2,1]^T (x) [1,0,-1]; sobel_v = transpose.
    // dx[r][jo] = b[r][jo] - b[r][jo+2]; sx[r][jo] = b[r][jo] + 2 b[r][jo+1] + b[r][jo+2]
    float dx[6][4], sx[6][4];
    #pragma unroll
    for (int r = 0; r < 6; r++)
        #pragma unroll
        for (int jo = 0; jo < 4; jo++) {
            dx[r][jo] = b[r][jo] - b[r][jo + 2];
            sx[r][jo] = b[r][jo] + 2.f * b[r][jo + 1] + b[r][jo + 2];
        }

    #pragma unroll
    for (int ro = 0; ro < 4; ro++) {
        float4 ov;
        float* pv = &ov.x;
        #pragma unroll
        for (int jo = 0; jo < 4; jo++) {
            const float gx = dx[ro][jo] + 2.f * dx[ro + 1][jo] + dx[ro + 2][jo];
            const float gy = sx[ro][jo] - sx[ro + 2][jo];
            const float mag = sqrtf(gx * gx + gy * gy);
            pv[jo] = (mag < 2.0f) ? 0.0f : mag;
        }
        *(float4*)(o + (long)(y0 + 4 * ty + ro) * W + x0 + 4 * tx) = ov;
    }
}

extern "C" void kernel_launch(void* const* d_in, const int* in_sizes, int n_in,
                              void* d_out, int out_size) {
    // metadata order: img, gauss_h, gauss_v, sobel_h, sobel_v, dir_w
    const float* img     = (const float*)d_in[0];
    const float* gauss_h = (const float*)d_in[1];
    float* out = (float*)d_out;

    const int W = 1024, H = 1024;
    const int N = in_sizes[0] / (W * H);

    dim3 block(32, 8, 1);
    dim3 grid(W / TX, H / TY, N);
    canny_fused_v2<<<grid, block>>>(img, gauss_h, out, W, H);
}

// round 7
// speedup vs baseline: 1.9819x; 1.1778x over previous
#include <cuda_runtime.h>

// Fused Canny front-end (separable 5-tap Gaussian + Sobel + magnitude threshold).
// Reference's NMS/orientation path is dead code w.r.t. the returned tensor.
//
// v3: - stage0 (raw tile smem) eliminated: horizontal gaussian reads global
//       directly (3 overlapping LDG.128 per f4 output, L1-cached).
//     - stage2 reads ONE float4/row/thread; vertical gaussian on 4 owned
//       columns; blurred halo columns exchanged via warp shuffle; lanes 0/31
//       compute the tile-edge halo column from a scalar smem read.
// Boundary semantics: reference zero-pads the *blurred* tensor before Sobel,
// so blurred values outside [0,H)x[0,W) are masked to 0 (edge CTAs only).

#define TXW 128
#define TYH 32
#define NROWS 38          // sB rows: image y0-3 .. y0+34
#define BF4   34          // sB f4 per row: floats j=0..135, image x = x0-4+j

__global__ __launch_bounds__(256, 4) void canny_fused_v3(
    const float* __restrict__ img,
    const float* __restrict__ g5,
    float* __restrict__ out,
    int W, int H)
{
    __shared__ float4 sB[NROWS * BF4];   // horizontal-gauss intermediate

    const int tx = threadIdx.x;          // 0..31
    const int ty = threadIdx.y;          // 0..7
    const int t  = ty * 32 + tx;
    const int x0 = blockIdx.x * TXW;
    const int y0 = blockIdx.y * TYH;
    const long plane = (long)W * H;
    const float* im = img + (long)blockIdx.z * plane;
    float* o = out + (long)blockIdx.z * plane;

    const float g0 = __ldg(g5 + 0), g1 = __ldg(g5 + 1), g2 = __ldg(g5 + 2),
                g3 = __ldg(g5 + 3), g4 = __ldg(g5 + 4);

    // ---- stage A: fused global load + horizontal gaussian -> sB ----
    // output f4 q covers floats j=4q..4q+3 (image x = x0-4+4q ..); needs raw
    // image floats x0-8+4q .. x0+3+4q  => three aligned float4 loads.
    #pragma unroll 2
    for (int i = t; i < NROWS * BF4; i += 256) {
        const int r = i / BF4;
        const int q = i - r * BF4;
        const int gy = y0 + r - 3;
        const int xa = x0 - 8 + 4 * q;
        const bool yv = (unsigned)gy < (unsigned)H;
        const float* rowp = im + (long)gy * W;
        float4 A = make_float4(0.f, 0.f, 0.f, 0.f), B = A, C = A;
        if (yv && (unsigned)xa < (unsigned)W)        A = *(const float4*)(rowp + xa);
        if (yv && (unsigned)(xa + 4) < (unsigned)W)  B = *(const float4*)(rowp + xa + 4);
        if (yv && (unsigned)(xa + 8) < (unsigned)W)  C = *(const float4*)(rowp + xa + 8);
        float4 oo;
        oo.x = g0 * A.z + g1 * A.w + g2 * B.x + g3 * B.y + g4 * B.z;
        oo.y = g0 * A.w + g1 * B.x + g2 * B.y + g3 * B.z + g4 * B.w;
        oo.z = g0 * B.x + g1 * B.y + g2 * B.z + g3 * B.w + g4 * C.x;
        oo.w = g0 * B.y + g1 * B.z + g2 * B.w + g3 * C.x + g4 * C.y;
        sB[i] = oo;
    }
    __syncthreads();

    // ---- stage B: vertical gaussian (registers) + halo shuffle + sobel ----
    // Thread patch: output rows y0+4ty..+3, cols x0+4tx..+3.
    // Owned blurred cols x0+4tx..+3  <=> sB floats j=4tx+4..4tx+7 = f4 idx tx+1.
    // Edge halo col: lane 0 needs x0-1 (j=3, float idx 3); lane 31 needs
    // x0+128 (j=132). Interior halos come from neighbor lanes' blurred values.
    const float gt[5] = {g0, g1, g2, g3, g4};
    const float* sBf = (const float*)sB;
    const int row0 = 4 * ty;
    const int eoff = (tx == 0) ? 3 : 132;

    float b[6][4], be[6];
    #pragma unroll
    for (int r = 0; r < 6; r++) {
        be[r] = 0.f;
        #pragma unroll
        for (int j = 0; j < 4; j++) b[r][j] = 0.f;
    }

    #pragma unroll
    for (int k = 0; k < 10; k++) {
        const float4 f = sB[(row0 + k) * BF4 + tx + 1];
        const float  e = sBf[(row0 + k) * (BF4 * 4) + eoff];
        #pragma unroll
        for (int br = 0; br < 6; br++) {
            const int ki = k - br;
            if (ki >= 0 && ki < 5) {
                const float gg = gt[ki];
                b[br][0] += gg * f.x;  b[br][1] += gg * f.y;
                b[br][2] += gg * f.z;  b[br][3] += gg * f.w;
                be[br]   += gg * e;
            }
        }
    }

    // y-mask: blurred rows outside image -> 0 (reference zero-pads blurred).
    if (y0 == 0 || y0 + TYH == H) {
        const int by = y0 + row0 - 1;
        #pragma unroll
        for (int r = 0; r < 6; r++) {
            if ((unsigned)(by + r) >= (unsigned)H) {
                b[r][0] = b[r][1] = b[r][2] = b[r][3] = 0.f;
                be[r] = 0.f;
            }
        }
    }

    // Halo columns via warp shuffle of blurred values.
    float L[6], R[6];
    const bool lzero = (x0 == 0) && (tx == 0);            // x = -1
    const bool rzero = (x0 + TXW == W) && (tx == 31);     // x = W
    #pragma unroll
    for (int r = 0; r < 6; r++) {
        const float lu = __shfl_up_sync(0xffffffffu, b[r][3], 1);
        const float rd = __shfl_down_sync(0xffffffffu, b[r][0], 1);
        L[r] = (tx == 0)  ? (lzero ? 0.f : be[r]) : lu;
        R[r] = (tx == 31) ? (rzero ? 0.f : be[r]) : rd;
    }

    // Separable sobel: sobel_h = [1,2,1]^T (x) [1,0,-1]; sobel_v = transpose.
    // Columns c0..c5 = L, b0..b3, R.
    float dx[6][4], sx[6][4];
    #pragma unroll
    for (int r = 0; r < 6; r++) {
        const float c0 = L[r], c1 = b[r][0], c2 = b[r][1],
                    c3 = b[r][2], c4 = b[r][3], c5 = R[r];
        dx[r][0] = c0 - c2;  sx[r][0] = c0 + 2.f * c1 + c2;
        dx[r][1] = c1 - c3;  sx[r][1] = c1 + 2.f * c2 + c3;
        dx[r][2] = c2 - c4;  sx[r][2] = c2 + 2.f * c3 + c4;
        dx[r][3] = c3 - c5;  sx[r][3] = c3 + 2.f * c4 + c5;
    }

    #pragma unroll
    for (int ro = 0; ro < 4; ro++) {
        float4 ov;
        float* pv = &ov.x;
        #pragma unroll
        for (int jo = 0; jo < 4; jo++) {
            const float gx = dx[ro][jo] + 2.f * dx[ro + 1][jo] + dx[ro + 2][jo];
            const float gy = sx[ro][jo] - sx[ro + 2][jo];
            const float mag = sqrtf(gx * gx + gy * gy);
            pv[jo] = (mag < 2.0f) ? 0.0f : mag;
        }
        *(float4*)(o + (long)(y0 + row0 + ro) * W + x0 + 4 * tx) = ov;
    }
}

extern "C" void kernel_launch(void* const* d_in, const int* in_sizes, int n_in,
                              void* d_out, int out_size) {
    // metadata order: img, gauss_h, gauss_v, sobel_h, sobel_v, dir_w
    const float* img     = (const float*)d_in[0];
    const float* gauss_h = (const float*)d_in[1];
    float* out = (float*)d_out;

    const int W = 1024, H = 1024;
    const int N = in_sizes[0] / (W * H);

    dim3 block(32, 8, 1);
    dim3 grid(W / TXW, H / TYH, N);
    canny_fused_v3<<<grid, block>>>(img, gauss_h, out, W, H);
}

// round 8
// speedup vs baseline: 1.9875x; 1.0028x over previous
#include <cuda_runtime.h>

// Fused Canny front-end (separable 5-tap Gaussian + Sobel + magnitude threshold).
// Reference's NMS/orientation path is dead code w.r.t. the returned tensor.
//
// v4: - interior/border CTA template specialization (no predication on 70% of CTAs)
//     - stage A: pair-of-f4 processing (4 LDG.128 per 2 outputs), shift indexing,
//       separate sE[] array for the two tile-edge halo columns
//     - f32x2 packed FMA (PTX fma/add/mul.rn.f32x2) for vertical gaussian + sobel
// Boundary semantics: reference zero-pads the *blurred* tensor before Sobel,
// so blurred values outside [0,H)x[0,W) are masked to 0 (border CTAs only).

typedef unsigned long long u64;

__device__ __forceinline__ u64 pk2(float lo, float hi) {
    u64 r; asm("mov.b64 %0, {%1, %2};" : "=l"(r) : "f"(lo), "f"(hi)); return r;
}
__device__ __forceinline__ void upk2(u64 v, float& lo, float& hi) {
    asm("mov.b64 {%0, %1}, %2;" : "=f"(lo), "=f"(hi) : "l"(v));
}
__device__ __forceinline__ u64 fma2_(u64 a, u64 b, u64 c) {
    u64 d; asm("fma.rn.f32x2 %0, %1, %2, %3;" : "=l"(d) : "l"(a), "l"(b), "l"(c)); return d;
}
__device__ __forceinline__ u64 add2_(u64 a, u64 b) {
    u64 d; asm("add.rn.f32x2 %0, %1, %2;" : "=l"(d) : "l"(a), "l"(b)); return d;
}
__device__ __forceinline__ u64 mul2_(u64 a, u64 b) {
    u64 d; asm("mul.rn.f32x2 %0, %1, %2;" : "=l"(d) : "l"(a), "l"(b)); return d;
}

#define NROWS 38        // sB rows: image y = y0-3 .. y0+34

template<bool BORDER>
__device__ __forceinline__ void canny_body(
    const float* __restrict__ im, float* __restrict__ o,
    float g0, float g1, float g2, float g3, float g4,
    int x0, int y0, int W, int H,
    float4* sB, float* sE, int tx, int ty, int t)
{
    // ---- stage A: fused global load + horizontal gaussian ----
    // sB[r*32+q] holds blurred-h at image cols x0+4q .. x0+4q+3.
    // Pair p = (r, qp): outputs q = 2qp, 2qp+1; raw floats x0+8qp-4 .. x0+8qp+11.
    #pragma unroll
    for (int i = t; i < NROWS * 16; i += 256) {
        const int r  = i >> 4;
        const int qp = i & 15;
        const int gy = y0 + r - 3;
        const int xa = x0 + 8 * qp - 4;
        const float* rowp = im + (long)gy * W + xa;
        float4 A, B, C, D;
        if (!BORDER) {
            A = *(const float4*)(rowp);
            B = *(const float4*)(rowp + 4);
            C = *(const float4*)(rowp + 8);
            D = *(const float4*)(rowp + 12);
        } else {
            A = make_float4(0.f, 0.f, 0.f, 0.f); B = A; C = A; D = A;
            const bool yv = (unsigned)gy < (unsigned)H;
            if (yv && (unsigned)xa        < (unsigned)W) A = *(const float4*)(rowp);
            if (yv && (unsigned)(xa + 4)  < (unsigned)W) B = *(const float4*)(rowp + 4);
            if (yv && (unsigned)(xa + 8)  < (unsigned)W) C = *(const float4*)(rowp + 8);
            if (yv && (unsigned)(xa + 12) < (unsigned)W) D = *(const float4*)(rowp + 12);
        }
        float4 o1, o2;
        o1.x = g0 * A.z + g1 * A.w + g2 * B.x + g3 * B.y + g4 * B.z;
        o1.y = g0 * A.w + g1 * B.x + g2 * B.y + g3 * B.z + g4 * B.w;
        o1.z = g0 * B.x + g1 * B.y + g2 * B.z + g3 * B.w + g4 * C.x;
        o1.w = g0 * B.y + g1 * B.z + g2 * B.w + g3 * C.x + g4 * C.y;
        o2.x = g0 * B.z + g1 * B.w + g2 * C.x + g3 * C.y + g4 * C.z;
        o2.y = g0 * B.w + g1 * C.x + g2 * C.y + g3 * C.z + g4 * C.w;
        o2.z = g0 * C.x + g1 * C.y + g2 * C.z + g3 * C.w + g4 * D.x;
        o2.w = g0 * C.y + g1 * C.z + g2 * C.w + g3 * D.x + g4 * D.y;
        sB[r * 32 + 2 * qp]     = o1;
        sB[r * 32 + 2 * qp + 1] = o2;
    }
    // Edge halo columns: sE[2r+0] = hgauss at x0-1, sE[2r+1] = hgauss at x0+128.
    if (t < NROWS * 2) {
        const int r = t >> 1, side = t & 1;
        const int gy = y0 + r - 3;
        const int xc = side ? (x0 + 128) : (x0 - 1);
        float v = 0.f;
        if (!BORDER) {
            const float* p = im + (long)gy * W + (xc - 2);
            v = g0 * p[0] + g1 * p[1] + g2 * p[2] + g3 * p[3] + g4 * p[4];
        } else if ((unsigned)gy < (unsigned)H) {
            const float* p = im + (long)gy * W;
            const float gg[5] = {g0, g1, g2, g3, g4};
            #pragma unroll
            for (int j = 0; j < 5; j++) {
                const int x = xc - 2 + j;
                if ((unsigned)x < (unsigned)W) v = fmaf(gg[j], p[x], v);
            }
        }
        sE[t] = v;
    }
    __syncthreads();

    // ---- stage B: vertical gaussian (packed f32x2) + halo shuffle + sobel ----
    // Thread patch: output rows y0+4ty..+3, cols x0+4tx..+3 (sB f4 idx tx).
    const int row0 = 4 * ty;
    const float gt[5] = {g0, g1, g2, g3, g4};
    u64 pg[5];
    #pragma unroll
    for (int i = 0; i < 5; i++) pg[i] = pk2(gt[i], gt[i]);

    u64 acc[6][2];
    float be[6];
    #pragma unroll
    for (int r = 0; r < 6; r++) { acc[r][0] = 0ull; acc[r][1] = 0ull; be[r] = 0.f; }

    const int eidx = (tx == 0) ? 0 : 1;
    #pragma unroll
    for (int k = 0; k < 10; k++) {
        const float4 f = sB[(row0 + k) * 32 + tx];
        const float  e = sE[(row0 + k) * 2 + eidx];
        const u64 flo = pk2(f.x, f.y);
        const u64 fhi = pk2(f.z, f.w);
        #pragma unroll
        for (int br = 0; br < 6; br++) {
            const int ki = k - br;
            if (ki >= 0 && ki < 5) {
                acc[br][0] = fma2_(pg[ki], flo, acc[br][0]);
                acc[br][1] = fma2_(pg[ki], fhi, acc[br][1]);
                be[br] = fmaf(gt[ki], e, be[br]);
            }
        }
    }

    // y-mask: blurred rows outside image -> 0 (reference zero-pads blurred).
    if (BORDER && (y0 == 0 || y0 + 32 == H)) {
        const int by = y0 + row0 - 1;
        #pragma unroll
        for (int r = 0; r < 6; r++)
            if ((unsigned)(by + r) >= (unsigned)H) {
                acc[r][0] = 0ull; acc[r][1] = 0ull; be[r] = 0.f;
            }
    }

    // Halo columns + sobel, rolling 3-row window.
    // Row r columns: c0=L, c1..c4 = owned b0..b3, c5=R.
    // sobel_h = [1,2,1]^T (x) [1,0,-1]; sobel_v = transpose.
    const u64 TWO2  = pk2(2.f, 2.f);
    const u64 NEG12 = pk2(-1.f, -1.f);
    const bool lz = BORDER && (x0 == 0);
    const bool rz = BORDER && (x0 + 128 == W);

    u64 dxp[6][2], sxp[6][2];
    #pragma unroll
    for (int r = 0; r < 6; r++) {
        float b0, b1, b2, b3;
        upk2(acc[r][0], b0, b1);
        upk2(acc[r][1], b2, b3);
        const float lu = __shfl_up_sync(0xffffffffu, b3, 1);
        const float rd = __shfl_down_sync(0xffffffffu, b0, 1);
        const float L = (tx == 0)  ? (lz ? 0.f : be[r]) : lu;
        const float R = (tx == 31) ? (rz ? 0.f : be[r]) : rd;

        const u64 P01 = pk2(L, b0);       // (c0,c1)
        const u64 P12 = acc[r][0];        // (c1,c2)
        const u64 P23 = pk2(b1, b2);      // (c2,c3)
        const u64 P34 = acc[r][1];        // (c3,c4)
        const u64 P45 = pk2(b3, R);       // (c4,c5)

        dxp[r][0] = fma2_(P23, NEG12, P01);                 // (c0-c2, c1-c3)
        dxp[r][1] = fma2_(P45, NEG12, P23);                 // (c2-c4, c3-c5)
        sxp[r][0] = fma2_(TWO2, P12, add2_(P01, P23));      // c+2c+c, shifted
        sxp[r][1] = fma2_(TWO2, P34, add2_(P23, P45));
    }

    #pragma unroll
    for (int ro = 0; ro < 4; ro++) {
        const u64 gx0 = add2_(dxp[ro][0], fma2_(TWO2, dxp[ro + 1][0], dxp[ro + 2][0]));
        const u64 gx1 = add2_(dxp[ro][1], fma2_(TWO2, dxp[ro + 1][1], dxp[ro + 2][1]));
        const u64 gy0 = fma2_(sxp[ro + 2][0], NEG12, sxp[ro][0]);
        const u64 gy1 = fma2_(sxp[ro + 2][1], NEG12, sxp[ro][1]);
        const u64 m0 = fma2_(gy0, gy0, mul2_(gx0, gx0));
        const u64 m1 = fma2_(gy1, gy1, mul2_(gx1, gx1));
        float ms[4];
        upk2(m0, ms[0], ms[1]);
        upk2(m1, ms[2], ms[3]);
        float4 ov;
        float* pv = &ov.x;
        #pragma unroll
        for (int jo = 0; jo < 4; jo++) {
            const float mag = sqrtf(ms[jo]);
            pv[jo] = (mag < 2.0f) ? 0.0f : mag;
        }
        *(float4*)(o + (long)(y0 + row0 + ro) * W + x0 + 4 * tx) = ov;
    }
}

__global__ __launch_bounds__(256) void canny_fused_v4(
    const float* __restrict__ img,
    const float* __restrict__ g5,
    float* __restrict__ out,
    int W, int H)
{
    __shared__ float4 sB[NROWS * 32];   // 19456 B
    __shared__ float  sE[NROWS * 2];

    const int tx = threadIdx.x;
    const int ty = threadIdx.y;
    const int t  = ty * 32 + tx;
    const int x0 = blockIdx.x * 128;
    const int y0 = blockIdx.y * 32;
    const long plane = (long)W * H;
    const float* im = img + (long)blockIdx.z * plane;
    float* o = out + (long)blockIdx.z * plane;

    const float g0 = __ldg(g5 + 0), g1 = __ldg(g5 + 1), g2 = __ldg(g5 + 2),
                g3 = __ldg(g5 + 3), g4 = __ldg(g5 + 4);

    const bool border = (blockIdx.x == 0) | (blockIdx.x == gridDim.x - 1) |
                        (blockIdx.y == 0) | (blockIdx.y == gridDim.y - 1);
    if (border)
        canny_body<true >(im, o, g0, g1, g2, g3, g4, x0, y0, W, H, sB, sE, tx, ty, t);
    else
        canny_body<false>(im, o, g0, g1, g2, g3, g4, x0, y0, W, H, sB, sE, tx, ty, t);
}

extern "C" void kernel_launch(void* const* d_in, const int* in_sizes, int n_in,
                              void* d_out, int out_size) {
    // metadata order: img, gauss_h, gauss_v, sobel_h, sobel_v, dir_w
    const float* img     = (const float*)d_in[0];
    const float* gauss_h = (const float*)d_in[1];
    float* out = (float*)d_out;

    const int W = 1024, H = 1024;
    const int N = in_sizes[0] / (W * H);

    dim3 block(32, 8, 1);
    dim3 grid(W / 128, H / 32, N);
    canny_fused_v4<<<grid, block>>>(img, gauss_h, out, W, H);
}

// round 9
// speedup vs baseline: 2.1459x; 1.0797x over previous
#include <cuda_runtime.h>

// Fused Canny front-end (separable 5-tap Gaussian + Sobel + magnitude threshold).
// Reference's NMS/orientation path is dead code w.r.t. the returned tensor.
//
// v5: - stage A coalesced: one sB row per warp, lane-per-f4 LDG.128 (contiguous),
//       halo via 4 warp shuffles; lanes 0/31 load one edge f4 and compute the
//       sE halo hgauss columns in-register.
//     - rolling 3-row sobel window + __launch_bounds__(256,5) -> 5 CTAs/SM.
//     - threshold on squared magnitude + m*rsqrtf(m) (MUFU.RSQ) instead of sqrtf.
// Boundary semantics: reference zero-pads the *blurred* tensor before Sobel,
// so blurred values outside [0,H)x[0,W) are masked to 0 (border CTAs only).

typedef unsigned long long u64;

__device__ __forceinline__ u64 pk2(float lo, float hi) {
    u64 r; asm("mov.b64 %0, {%1, %2};" : "=l"(r) : "f"(lo), "f"(hi)); return r;
}
__device__ __forceinline__ void upk2(u64 v, float& lo, float& hi) {
    asm("mov.b64 {%0, %1}, %2;" : "=f"(lo), "=f"(hi) : "l"(v));
}
__device__ __forceinline__ u64 fma2_(u64 a, u64 b, u64 c) {
    u64 d; asm("fma.rn.f32x2 %0, %1, %2, %3;" : "=l"(d) : "l"(a), "l"(b), "l"(c)); return d;
}
__device__ __forceinline__ u64 add2_(u64 a, u64 b) {
    u64 d; asm("add.rn.f32x2 %0, %1, %2;" : "=l"(d) : "l"(a), "l"(b)); return d;
}
__device__ __forceinline__ u64 mul2_(u64 a, u64 b) {
    u64 d; asm("mul.rn.f32x2 %0, %1, %2;" : "=l"(d) : "l"(a), "l"(b)); return d;
}

#define NROWS 38        // sB rows: image y = y0-3 .. y0+34

template<bool BORDER>
__device__ __forceinline__ void canny_body(
    const float* __restrict__ im, float* __restrict__ o,
    float g0, float g1, float g2, float g3, float g4,
    int x0, int y0, int W, int H,
    float4* sB, float* sE, int tx, int ty)
{
    // ---- stage A: fused coalesced load + horizontal gaussian ----
    // One sB row per warp per iter. Lane tx owns output f4 at image cols
    // x0+4tx..+3, loads exactly that f4; halo floats come from lane shuffles.
    const bool le = (tx == 0), re = (tx == 31);
    #pragma unroll
    for (int r = ty; r < NROWS; r += 8) {
        const int gy = y0 + r - 3;
        const float* rowp = im + (long)gy * W + x0;
        float4 m4 = make_float4(0.f, 0.f, 0.f, 0.f);
        float4 e4 = m4;
        const int eoff = le ? -4 : 128;
        if (!BORDER) {
            m4 = *(const float4*)(rowp + 4 * tx);
            if (le | re) e4 = *(const float4*)(rowp + eoff);
        } else {
            const bool rowv = (unsigned)gy < (unsigned)H;
            if (rowv) {
                m4 = *(const float4*)(rowp + 4 * tx);
                if ((le | re) && (unsigned)(x0 + eoff) < (unsigned)W)
                    e4 = *(const float4*)(rowp + eoff);
            }
        }
        // halo floats: pz,pw = in[x-2],in[x-1] ; nx,ny = in[x+4],in[x+5]
        float pz = __shfl_up_sync(0xffffffffu, m4.z, 1);
        float pw = __shfl_up_sync(0xffffffffu, m4.w, 1);
        float nx = __shfl_down_sync(0xffffffffu, m4.x, 1);
        float ny = __shfl_down_sync(0xffffffffu, m4.y, 1);
        if (le) { pz = e4.z; pw = e4.w; }
        if (re) { nx = e4.x; ny = e4.y; }

        float4 oo;
        oo.x = g0 * pz   + g1 * pw   + g2 * m4.x + g3 * m4.y + g4 * m4.z;
        oo.y = g0 * pw   + g1 * m4.x + g2 * m4.y + g3 * m4.z + g4 * m4.w;
        oo.z = g0 * m4.x + g1 * m4.y + g2 * m4.z + g3 * m4.w + g4 * nx;
        oo.w = g0 * m4.y + g1 * m4.z + g2 * m4.w + g3 * nx   + g4 * ny;
        sB[r * 32 + tx] = oo;

        // tile-edge hgauss halo columns (x0-1 and x0+128)
        if (le) sE[2 * r]     = g0 * e4.y + g1 * e4.z + g2 * e4.w + g3 * m4.x + g4 * m4.y;
        if (re) sE[2 * r + 1] = g0 * m4.z + g1 * m4.w + g2 * e4.x + g3 * e4.y + g4 * e4.z;
    }
    __syncthreads();

    // ---- stage B: vertical gaussian (packed f32x2) -> rolling sobel ----
    const int row0 = 4 * ty;
    const float gt[5] = {g0, g1, g2, g3, g4};
    u64 pg[5];
    #pragma unroll
    for (int i = 0; i < 5; i++) pg[i] = pk2(gt[i], gt[i]);

    u64 acc[6][2];
    float be[6];
    #pragma unroll
    for (int r = 0; r < 6; r++) { acc[r][0] = 0ull; acc[r][1] = 0ull; be[r] = 0.f; }

    const int eidx = le ? 0 : 1;
    #pragma unroll
    for (int k = 0; k < 10; k++) {
        const float4 f = sB[(row0 + k) * 32 + tx];
        const float  e = sE[(row0 + k) * 2 + eidx];
        const u64 flo = pk2(f.x, f.y);
        const u64 fhi = pk2(f.z, f.w);
        #pragma unroll
        for (int br = 0; br < 6; br++) {
            const int ki = k - br;
            if (ki >= 0 && ki < 5) {
                acc[br][0] = fma2_(pg[ki], flo, acc[br][0]);
                acc[br][1] = fma2_(pg[ki], fhi, acc[br][1]);
                be[br] = fmaf(gt[ki], e, be[br]);
            }
        }
    }

    // y-mask: blurred rows outside image -> 0 (reference zero-pads blurred).
    if (BORDER && (y0 == 0 || y0 + 32 == H)) {
        const int by = y0 + row0 - 1;
        #pragma unroll
        for (int r = 0; r < 6; r++)
            if ((unsigned)(by + r) >= (unsigned)H) {
                acc[r][0] = 0ull; acc[r][1] = 0ull; be[r] = 0.f;
            }
    }

    const u64 TWO2  = pk2(2.f, 2.f);
    const u64 NEG12 = pk2(-1.f, -1.f);
    const bool lz = BORDER && (x0 == 0);
    const bool rz = BORDER && (x0 + 128 == W);

    // per-row dx/sx pair computation (warp-uniform: contains shuffles)
    #define ROW_DS(RI, D0, D1, S0, S1) do {                                   \
        float b0, b1, b2, b3;                                                 \
        upk2(acc[RI][0], b0, b1);                                             \
        upk2(acc[RI][1], b2, b3);                                             \
        const float lu = __shfl_up_sync(0xffffffffu, b3, 1);                  \
        const float rd = __shfl_down_sync(0xffffffffu, b0, 1);                \
        const float L = le ? (lz ? 0.f : be[RI]) : lu;                        \
        const float R = re ? (rz ? 0.f : be[RI]) : rd;                        \
        const u64 P01 = pk2(L, b0);                                           \
        const u64 P23 = pk2(b1, b2);                                          \
        const u64 P45 = pk2(b3, R);                                           \
        D0 = fma2_(P23, NEG12, P01);                                          \
        D1 = fma2_(P45, NEG12, P23);                                          \
        S0 = fma2_(TWO2, acc[RI][0], add2_(P01, P23));                        \
        S1 = fma2_(TWO2, acc[RI][1], add2_(P23, P45));                        \
    } while (0)

    #define EMIT(RO, DA0, DA1, DB0, DB1, DC0, DC1, SA0, SA1, SC0, SC1) do {   \
        const u64 gx0 = add2_(DA0, fma2_(TWO2, DB0, DC0));                    \
        const u64 gx1 = add2_(DA1, fma2_(TWO2, DB1, DC1));                    \
        const u64 gy0 = fma2_(SC0, NEG12, SA0);                               \
        const u64 gy1 = fma2_(SC1, NEG12, SA1);                               \
        const u64 m0 = fma2_(gy0, gy0, mul2_(gx0, gx0));                      \
        const u64 m1 = fma2_(gy1, gy1, mul2_(gx1, gx1));                      \
        float ms0, ms1, ms2, ms3;                                             \
        upk2(m0, ms0, ms1);                                                   \
        upk2(m1, ms2, ms3);                                                   \
        float4 ov;                                                            \
        ov.x = (ms0 < 4.0f) ? 0.0f : ms0 * rsqrtf(ms0);                       \
        ov.y = (ms1 < 4.0f) ? 0.0f : ms1 * rsqrtf(ms1);                       \
        ov.z = (ms2 < 4.0f) ? 0.0f : ms2 * rsqrtf(ms2);                       \
        ov.w = (ms3 < 4.0f) ? 0.0f : ms3 * rsqrtf(ms3);                       \
        *(float4*)(o + (long)(y0 + row0 + (RO)) * W + x0 + 4 * tx) = ov;      \
    } while (0)

    u64 d00, d01, s00, s01, d10, d11, s10, s11, d20, d21, s20, s21;
    ROW_DS(0, d00, d01, s00, s01);
    ROW_DS(1, d10, d11, s10, s11);
    ROW_DS(2, d20, d21, s20, s21);
    EMIT(0, d00, d01, d10, d11, d20, d21, s00, s01, s20, s21);
    ROW_DS(3, d00, d01, s00, s01);
    EMIT(1, d10, d11, d20, d21, d00, d01, s10, s11, s00, s01);
    ROW_DS(4, d10, d11, s10, s11);
    EMIT(2, d20, d21, d00, d01, d10, d11, s20, s21, s10, s11);
    ROW_DS(5, d20, d21, s20, s21);
    EMIT(3, d00, d01, d10, d11, d20, d21, s00, s01, s20, s21);

    #undef ROW_DS
    #undef EMIT
}

__global__ __launch_bounds__(256, 5) void canny_fused_v5(
    const float* __restrict__ img,
    const float* __restrict__ g5,
    float* __restrict__ out,
    int W, int H)
{
    __shared__ float4 sB[NROWS * 32];   // 19456 B
    __shared__ float  sE[NROWS * 2];

    const int tx = threadIdx.x;
    const int ty = threadIdx.y;
    const int x0 = blockIdx.x * 128;
    const int y0 = blockIdx.y * 32;
    const long plane = (long)W * H;
    const float* im = img + (long)blockIdx.z * plane;
    float* o = out + (long)blockIdx.z * plane;

    const float g0 = __ldg(g5 + 0), g1 = __ldg(g5 + 1), g2 = __ldg(g5 + 2),
                g3 = __ldg(g5 + 3), g4 = __ldg(g5 + 4);

    const bool border = (blockIdx.x == 0) | (blockIdx.x == gridDim.x - 1) |
                        (blockIdx.y == 0) | (blockIdx.y == gridDim.y - 1);
    if (border)
        canny_body<true >(im, o, g0, g1, g2, g3, g4, x0, y0, W, H, sB, sE, tx, ty);
    else
        canny_body<false>(im, o, g0, g1, g2, g3, g4, x0, y0, W, H, sB, sE, tx, ty);
}

extern "C" void kernel_launch(void* const* d_in, const int* in_sizes, int n_in,
                              void* d_out, int out_size) {
    // metadata order: img, gauss_h, gauss_v, sobel_h, sobel_v, dir_w
    const float* img     = (const float*)d_in[0];
    const float* gauss_h = (const float*)d_in[1];
    float* out = (float*)d_out;

    const int W = 1024, H = 1024;
    const int N = in_sizes[0] / (W * H);

    dim3 block(32, 8, 1);
    dim3 grid(W / 128, H / 32, N);
    canny_fused_v5<<<grid, block>>>(img, gauss_h, out, W, H);
}

// round 10
// speedup vs baseline: 2.1820x; 1.0168x over previous
#include <cuda_runtime.h>

// Fused Canny front-end (separable 5-tap Gaussian + Sobel + magnitude threshold).
// Reference's NMS/orientation path is dead code w.r.t. the returned tensor.
//
// v6: stage-A hgauss grid shifted by -1 col so stage B reads its 6 blurred
// columns as three ALIGNED 64-bit pairs (1 LDS.128 + 1 LDS.64 per row):
//   A=(x-1,x)  B=(x+1,x+2)  C=(x+3,x+4)
// Vertical gaussian accumulates f32x2 on A/B/C directly; sobel dx = A-B, B-C.
// No shuffles, no scalar edge path, no pack/unpack chains in stage B.
// Boundary: reference zero-pads the *blurred* tensor before Sobel, so blurred
// values outside [0,H)x[0,W) are masked (y: row zero; x: 64-bit AND on edge lanes).

typedef unsigned long long u64;

__device__ __forceinline__ u64 pk2(float lo, float hi) {
    u64 r; asm("mov.b64 %0, {%1, %2};" : "=l"(r) : "f"(lo), "f"(hi)); return r;
}
__device__ __forceinline__ void upk2(u64 v, float& lo, float& hi) {
    asm("mov.b64 {%0, %1}, %2;" : "=f"(lo), "=f"(hi) : "l"(v));
}
__device__ __forceinline__ u64 fma2_(u64 a, u64 b, u64 c) {
    u64 d; asm("fma.rn.f32x2 %0, %1, %2, %3;" : "=l"(d) : "l"(a), "l"(b), "l"(c)); return d;
}
__device__ __forceinline__ u64 add2_(u64 a, u64 b) {
    u64 d; asm("add.rn.f32x2 %0, %1, %2;" : "=l"(d) : "l"(a), "l"(b)); return d;
}
__device__ __forceinline__ u64 mul2_(u64 a, u64 b) {
    u64 d; asm("mul.rn.f32x2 %0, %1, %2;" : "=l"(d) : "l"(a), "l"(b)); return d;
}

#define NROWS 38        // sB rows: image y = y0-3 .. y0+34
#define BSTR  34        // f4 stride per row (33 used + pad)

template<bool BORDER>
__device__ __forceinline__ void canny_body(
    const float* __restrict__ im, float* __restrict__ o,
    float g0, float g1, float g2, float g3, float g4,
    int x0, int y0, int W, int H,
    float4* sB, int tx, int ty)
{
    const bool le = (tx == 0), re = (tx == 31);

    // ---- stage A: coalesced load + SHIFTED horizontal gaussian ----
    // sB[r][tx] = hgauss at cols (x-1, x, x+1, x+2), x = x0+4tx.
    // sB[r][32].xy = hgauss at (x0+127, x0+128)  (written by lane 31).
    {
        const int eoff = le ? -4 : 128;
        const bool eok = !BORDER || ((unsigned)(x0 + eoff) < (unsigned)W);
        #pragma unroll
        for (int r = ty; r < NROWS; r += 8) {
            const int gy = y0 + r - 3;
            const float* rowp = im + (long)gy * W + x0;
            float4 m4 = make_float4(0.f, 0.f, 0.f, 0.f);
            float4 e4 = m4;
            if (!BORDER) {
                m4 = *(const float4*)(rowp + 4 * tx);
                if (le | re) e4 = *(const float4*)(rowp + eoff);
            } else {
                const bool rv = (unsigned)gy < (unsigned)H;
                if (rv) {
                    m4 = *(const float4*)(rowp + 4 * tx);
                    if ((le | re) && eok) e4 = *(const float4*)(rowp + eoff);
                }
            }
            // halo raw floats: py,pz,pw = in[x-3..x-1]; nx = in[x+4]
            float py = __shfl_up_sync(0xffffffffu, m4.y, 1);
            float pz = __shfl_up_sync(0xffffffffu, m4.z, 1);
            float pw = __shfl_up_sync(0xffffffffu, m4.w, 1);
            float nx = __shfl_down_sync(0xffffffffu, m4.x, 1);
            if (le) { py = e4.y; pz = e4.z; pw = e4.w; }
            if (re) { nx = e4.x; }

            float4 oo;
            oo.x = g0 * py   + g1 * pz   + g2 * pw   + g3 * m4.x + g4 * m4.y;  // x-1
            oo.y = g0 * pz   + g1 * pw   + g2 * m4.x + g3 * m4.y + g4 * m4.z;  // x
            oo.z = g0 * pw   + g1 * m4.x + g2 * m4.y + g3 * m4.z + g4 * m4.w;  // x+1
            oo.w = g0 * m4.x + g1 * m4.y + g2 * m4.z + g3 * m4.w + g4 * nx;    // x+2
            sB[r * BSTR + tx] = oo;

            // tile-edge extras (only lane 31's values are meaningful/stored)
            float hx = g0 * m4.y + g1 * m4.z + g2 * m4.w + g3 * e4.x + g4 * e4.y; // x0+127
            float hy = g0 * m4.z + g1 * m4.w + g2 * e4.x + g3 * e4.y + g4 * e4.z; // x0+128
            if (re) { float2 ex = make_float2(hx, hy); *(float2*)&sB[r * BSTR + 32] = ex; }
        }
    }
    __syncthreads();

    // ---- stage B: vertical gaussian on aligned pairs -> rolling sobel ----
    const int row0 = 4 * ty;
    u64 pg[5] = {pk2(g0, g0), pk2(g1, g1), pk2(g2, g2), pk2(g3, g3), pk2(g4, g4)};

    u64 aA[6], aB[6], aC[6];
    #pragma unroll
    for (int r = 0; r < 6; r++) { aA[r] = 0ull; aB[r] = 0ull; aC[r] = 0ull; }

    #pragma unroll
    for (int k = 0; k < 10; k++) {
        const float4* rp = &sB[(row0 + k) * BSTR + tx];
        const ulonglong2 AB = *(const ulonglong2*)rp;     // (c0,c1),(c2,c3)
        const u64 CC = *(const u64*)(rp + 1);             // (c4,c5)
        #pragma unroll
        for (int br = 0; br < 6; br++) {
            const int ki = k - br;
            if (ki >= 0 && ki < 5) {
                aA[br] = fma2_(pg[ki], AB.x, aA[br]);
                aB[br] = fma2_(pg[ki], AB.y, aB[br]);
                aC[br] = fma2_(pg[ki], CC,   aC[br]);
            }
        }
    }

    if (BORDER) {
        // y-mask: blurred rows outside image -> 0
        if (y0 == 0 || y0 + 32 == H) {
            const int by = y0 + row0 - 1;
            #pragma unroll
            for (int r = 0; r < 6; r++)
                if ((unsigned)(by + r) >= (unsigned)H) { aA[r] = 0ull; aB[r] = 0ull; aC[r] = 0ull; }
        }
        // x-mask: blurred col x0-1 (A.lo, lane 0) / x0+128 (C.hi, lane 31) -> 0
        if (x0 == 0 && le) {
            #pragma unroll
            for (int r = 0; r < 6; r++) aA[r] &= 0xFFFFFFFF00000000ull;
        }
        if (x0 + 128 == W && re) {
            #pragma unroll
            for (int r = 0; r < 6; r++) aC[r] &= 0x00000000FFFFFFFFull;
        }
    }

    const u64 TWO2  = pk2(2.f, 2.f);
    const u64 NEG12 = pk2(-1.f, -1.f);
    float* po = o + (long)(y0 + row0) * W + x0 + 4 * tx;

    // dx pair1 = A - B, pair2 = B - C ; sx pair1 = (A+B) + 2*(a1,b0), pair2 = (B+C) + 2*(b1,c0)
    #define ROW_DS(RI, D1, D2, S1, S2) do {                                   \
        const u64 A_ = aA[RI], B_ = aB[RI], C_ = aC[RI];                      \
        D1 = fma2_(B_, NEG12, A_);                                            \
        D2 = fma2_(C_, NEG12, B_);                                            \
        float a0_, a1_, b0_, b1_, c0_, c1_;                                   \
        upk2(A_, a0_, a1_); upk2(B_, b0_, b1_); upk2(C_, c0_, c1_);           \
        S1 = fma2_(TWO2, pk2(a1_, b0_), add2_(A_, B_));                       \
        S2 = fma2_(TWO2, pk2(b1_, c0_), add2_(B_, C_));                       \
    } while (0)

    #define EMIT(DA1, DA2, DB1, DB2, DC1, DC2, SA1, SA2, SC1, SC2) do {       \
        const u64 gx0 = add2_(DA1, fma2_(TWO2, DB1, DC1));                    \
        const u64 gx1 = add2_(DA2, fma2_(TWO2, DB2, DC2));                    \
        const u64 gy0 = fma2_(SC1, NEG12, SA1);                               \
        const u64 gy1 = fma2_(SC2, NEG12, SA2);                               \
        const u64 m0 = fma2_(gy0, gy0, mul2_(gx0, gx0));                      \
        const u64 m1 = fma2_(gy1, gy1, mul2_(gx1, gx1));                      \
        float s0, s1, s2, s3;                                                 \
        upk2(m0, s0, s1); upk2(m1, s2, s3);                                   \
        float4 ov;                                                            \
        ov.x = (s0 < 4.0f) ? 0.0f : s0 * rsqrtf(s0);                          \
        ov.y = (s1 < 4.0f) ? 0.0f : s1 * rsqrtf(s1);                          \
        ov.z = (s2 < 4.0f) ? 0.0f : s2 * rsqrtf(s2);                          \
        ov.w = (s3 < 4.0f) ? 0.0f : s3 * rsqrtf(s3);                          \
        *(float4*)po = ov; po += W;                                           \
    } while (0)

    u64 d00, d01, s00, s01, d10, d11, s10, s11, d20, d21, s20, s21;
    ROW_DS(0, d00, d01, s00, s01);
    ROW_DS(1, d10, d11, s10, s11);
    ROW_DS(2, d20, d21, s20, s21);
    EMIT(d00, d01, d10, d11, d20, d21, s00, s01, s20, s21);
    ROW_DS(3, d00, d01, s00, s01);
    EMIT(d10, d11, d20, d21, d00, d01, s10, s11, s00, s01);
    ROW_DS(4, d10, d11, s10, s11);
    EMIT(d20, d21, d00, d01, d10, d11, s20, s21, s10, s11);
    ROW_DS(5, d20, d21, s20, s21);
    EMIT(d00, d01, d10, d11, d20, d21, s00, s01, s20, s21);

    #undef ROW_DS
    #undef EMIT
}

__global__ __launch_bounds__(256, 5) void canny_fused_v6(
    const float* __restrict__ img,
    const float* __restrict__ g5,
    float* __restrict__ out,
    int W, int H)
{
    __shared__ float4 sB[NROWS * BSTR];   // 20672 B

    const int tx = threadIdx.x;
    const int ty = threadIdx.y;
    const int x0 = blockIdx.x * 128;
    const int y0 = blockIdx.y * 32;
    const long plane = (long)W * H;
    const float* im = img + (long)blockIdx.z * plane;
    float* o = out + (long)blockIdx.z * plane;

    const float g0 = __ldg(g5 + 0), g1 = __ldg(g5 + 1), g2 = __ldg(g5 + 2),
                g3 = __ldg(g5 + 3), g4 = __ldg(g5 + 4);

    const bool border = (blockIdx.x == 0) | (blockIdx.x == gridDim.x - 1) |
                        (blockIdx.y == 0) | (blockIdx.y == gridDim.y - 1);
    if (border)
        canny_body<true >(im, o, g0, g1, g2, g3, g4, x0, y0, W, H, sB, tx, ty);
    else
        canny_body<false>(im, o, g0, g1, g2, g3, g4, x0, y0, W, H, sB, tx, ty);
}

extern "C" void kernel_launch(void* const* d_in, const int* in_sizes, int n_in,
                              void* d_out, int out_size) {
    // metadata order: img, gauss_h, gauss_v, sobel_h, sobel_v, dir_w
    const float* img     = (const float*)d_in[0];
    const float* gauss_h = (const float*)d_in[1];
    float* out = (float*)d_out;

    const int W = 1024, H = 1024;
    const int N = in_sizes[0] / (W * H);

    dim3 block(32, 8, 1);
    dim3 grid(W / 128, H / 32, N);
    canny_fused_v6<<<grid, block>>>(img, gauss_h, out, W, H);
}